// round 8
// baseline (speedup 1.0000x reference)
#include <cuda_runtime.h>
#include <cstddef>
#include <cstdint>

#define NEGV -1000000000.0f
#define HDIM 128
#define NMAX 12288
#define CAP  128            // max edges per dest row (Poisson mean 32)

__device__ float2   g_p[NMAX];          // per-node partials
__device__ int      g_cnt[NMAX];        // per-row edge count (zero at load; K2 re-zeroes)
__device__ uint2    g_bucket[NMAX * CAP];  // (source, weight-bits) per row

// K1: two independent block roles — node partials, and edge binning by dest row.
__global__ void __launch_bounds__(256)
prep_bin_kernel(const float* __restrict__ h,
                const int* __restrict__ sources,
                const int* __restrict__ dests,
                const float* __restrict__ weights,
                const float* __restrict__ W,
                int N, int E, int nPartBlks) {
    const int tid = threadIdx.x;
    const int bid = blockIdx.x;

    if (bid < nPartBlks) {
        // partials: 8 lanes/node, 4 nodes/warp, 32 nodes/block
        const int warp = tid >> 5;
        const int lane = tid & 31;
        const int sub  = lane & 7;
        const int grp  = lane >> 3;
        const int node = bid * 32 + warp * 4 + grp;
        if (node < N) {
            const float* hp = h + (size_t)node * HDIM + sub * 16;
            const float* wp = W + sub * 16;
            float ad = 0.0f, as = 0.0f;
            #pragma unroll
            for (int k = 0; k < 4; k++) {
                const float4 hv = *reinterpret_cast<const float4*>(hp + k * 4);
                const float4 wd = *reinterpret_cast<const float4*>(wp + k * 4);
                const float4 ws = *reinterpret_cast<const float4*>(wp + HDIM + k * 4);
                ad += hv.x * wd.x + hv.y * wd.y + hv.z * wd.z + hv.w * wd.w;
                as += hv.x * ws.x + hv.y * ws.y + hv.z * ws.z + hv.w * ws.w;
            }
            #pragma unroll
            for (int o = 4; o; o >>= 1) {
                ad += __shfl_xor_sync(0xffffffffu, ad, o);
                as += __shfl_xor_sync(0xffffffffu, as, o);
            }
            if (sub == 0) g_p[node] = make_float2(ad, as);
        }
    } else {
        // bin: one edge per thread
        const int e = (bid - nPartBlks) * 256 + tid;
        if (e < E) {
            const int s = sources[e];
            const int d = dests[e];
            const float w = weights[e];
            int slot = atomicAdd(&g_cnt[d], 1);
            if (slot < CAP) {
                g_bucket[d * CAP + slot] = make_uint2((uint32_t)s, __float_as_uint(w));
            }
        }
    }
}

// K2: one block per dest row — fill the row with NEG, then patch its edges.
// Patch stores hit L2 lines this block just wrote -> merge, no extra DRAM.
__global__ void __launch_bounds__(256)
fill_patch_kernel(const float* __restrict__ W,
                  const float* __restrict__ b,
                  float* __restrict__ out, int N) {
    const int d   = blockIdx.x;
    const int tid = threadIdx.x;

    __shared__ int   s_cnt;
    __shared__ float s_pdx;

    if (tid == 0) {
        int c = g_cnt[d];
        g_cnt[d] = 0;                    // restore invariant for next replay
        s_cnt = (c < CAP) ? c : CAP;
        s_pdx = g_p[d].x;
    }

    // fill: 48KB contiguous row, 12 float4 per thread, no bounds checks
    float4* row4 = reinterpret_cast<float4*>(out) + (size_t)d * (N / 4);
    const float4 v = make_float4(NEGV, NEGV, NEGV, NEGV);
    #pragma unroll
    for (int k = 0; k < 12; k++) {
        row4[k * 256 + tid] = v;
    }

    __syncthreads();   // order fill stores before patch stores (block scope)

    const int cnt = s_cnt;
    if (tid < cnt) {
        const float wW = __ldg(W + 2 * HDIM);
        const float bb = __ldg(b);
        const uint2 bs = g_bucket[d * CAP + tid];
        const int s = (int)bs.x;
        const float val = s_pdx + __ldg(&g_p[s]).y + __uint_as_float(bs.y) * wW + bb;
        out[(size_t)d * N + s] = val;
    }
}

extern "C" void kernel_launch(void* const* d_in, const int* in_sizes, int n_in,
                              void* d_out, int out_size) {
    const float* h       = (const float*)d_in[0];
    const int*   sources = (const int*)d_in[1];
    const int*   dests   = (const int*)d_in[2];
    const float* weights = (const float*)d_in[3];
    const float* W       = (const float*)d_in[4];
    const float* b       = (const float*)d_in[5];
    float* out = (float*)d_out;

    const int N = in_sizes[0] / HDIM;     // 12288
    const int E = in_sizes[1];            // 393216

    const int nPartBlks = (N + 31) / 32;          // 384
    const int nBinBlks  = (E + 255) / 256;        // 1536

    prep_bin_kernel<<<nPartBlks + nBinBlks, 256>>>(h, sources, dests, weights,
                                                   W, N, E, nPartBlks);
    fill_patch_kernel<<<N, 256>>>(W, b, out, N);
}

// round 9
// speedup vs baseline: 1.6055x; 1.6055x over previous
#include <cuda_runtime.h>
#include <cstddef>

#define NEGV -1000000000.0f
#define HDIM 128
#define NMAX 12288

// per-node partials: g_p[n].x = h[n].W[0:128), g_p[n].y = h[n].W[128:256)
__device__ float2 g_p[NMAX];

// Fused: blocks [0, nPartBlks) compute node partials; the rest fill `out`.
// Roles touch disjoint memory -> no intra-kernel ordering needed.
__global__ void __launch_bounds__(256)
prep_fill_kernel(const float* __restrict__ h,
                 const float* __restrict__ W,
                 float4* __restrict__ out,
                 int N, int n4, int nPartBlks) {
    const int tid = threadIdx.x;
    const int bid = blockIdx.x;

    if (bid < nPartBlks) {
        // partials: 8 lanes per node, 4 nodes/warp, 32 nodes/block
        const int warp = tid >> 5;
        const int lane = tid & 31;
        const int sub  = lane & 7;
        const int grp  = lane >> 3;
        const int node = bid * 32 + warp * 4 + grp;
        if (node < N) {
            const float* hp = h + (size_t)node * HDIM + sub * 16;
            const float* wp = W + sub * 16;
            float ad = 0.0f, as = 0.0f;
            #pragma unroll
            for (int k = 0; k < 4; k++) {
                const float4 hv = *reinterpret_cast<const float4*>(hp + k * 4);
                const float4 wd = *reinterpret_cast<const float4*>(wp + k * 4);
                const float4 ws = *reinterpret_cast<const float4*>(wp + HDIM + k * 4);
                ad += hv.x * wd.x + hv.y * wd.y + hv.z * wd.z + hv.w * wd.w;
                as += hv.x * ws.x + hv.y * ws.y + hv.z * ws.z + hv.w * ws.w;
            }
            #pragma unroll
            for (int o = 4; o; o >>= 1) {
                ad += __shfl_xor_sync(0xffffffffu, ad, o);
                as += __shfl_xor_sync(0xffffffffu, as, o);
            }
            if (sub == 0) g_p[node] = make_float2(ad, as);
        }
    } else {
        // fill: 4 float4 stores per thread, plain stores (6.98 TB/s measured)
        const int fbid = bid - nPartBlks;
        const float4 v = make_float4(NEGV, NEGV, NEGV, NEGV);
        const int base = fbid * 1024 + tid;
        #pragma unroll
        for (int k = 0; k < 4; k++) {
            int idx = base + k * 256;
            if (idx < n4) out[idx] = v;
        }
    }
}

// Scatter: ONE edge per thread (max warp parallelism; R3-measured ~9us).
__global__ void __launch_bounds__(256)
scatter_kernel(const int* __restrict__ sources,
               const int* __restrict__ dests,
               const float* __restrict__ weights,
               const float* __restrict__ W,
               const float* __restrict__ b,
               float* __restrict__ out, int E, int N) {
    const int e = blockIdx.x * blockDim.x + threadIdx.x;
    if (e >= E) return;
    const int s = sources[e];
    const int d = dests[e];
    const float2 pd = __ldg(&g_p[d]);
    const float2 ps = __ldg(&g_p[s]);
    const float val = pd.x + ps.y + weights[e] * __ldg(W + 2 * HDIM) + __ldg(b);
    out[(size_t)d * N + s] = val;
}

extern "C" void kernel_launch(void* const* d_in, const int* in_sizes, int n_in,
                              void* d_out, int out_size) {
    const float* h       = (const float*)d_in[0];
    const int*   sources = (const int*)d_in[1];
    const int*   dests   = (const int*)d_in[2];
    const float* weights = (const float*)d_in[3];
    const float* W       = (const float*)d_in[4];
    const float* b       = (const float*)d_in[5];
    float* out = (float*)d_out;

    const int N = in_sizes[0] / HDIM;     // 12288
    const int E = in_sizes[1];            // 393216

    long long total = (long long)N * N;
    int n4 = (int)(total >> 2);           // 37,748,736

    const int nPartBlks = (N + 31) / 32;            // 384
    const int nFillBlks = (n4 + 1023) / 1024;       // 36,864

    prep_fill_kernel<<<nPartBlks + nFillBlks, 256>>>(h, W, (float4*)out,
                                                     N, n4, nPartBlks);

    scatter_kernel<<<(E + 255) / 256, 256>>>(sources, dests, weights,
                                             W, b, out, E, N);
}